// round 1
// baseline (speedup 1.0000x reference)
#include <cuda_runtime.h>
#include <cuda_bf16.h>
#include <math.h>

// Problem constants
#define BATCH 16
#define C_IN  256
#define H_DIM 64
#define W_DIM 64
#define HW    4096     // 64*64
#define HWP   1024     // pooled 32*32
#define CK    32       // f/g channels
#define CH    128      // h channels
#define OC_TOT 192     // 32(f)+32(g)+128(h)

// Scratch (static device globals -- allocation is forbidden)
__device__ float d_y[(size_t)BATCH * OC_TOT * HW];   // proj output full res (~50MB)
__device__ float d_gbuf[(size_t)BATCH * CK * HWP];   // pooled g (2MB)
__device__ float d_hbuf[(size_t)BATCH * CH * HWP];   // pooled h (8MB)
__device__ float d_obuf[(size_t)BATCH * CH * HW];    // attention out (~33MB)

// ---------------------------------------------------------------------------
// Kernel 1: fused projection GEMM.  Y[b, oc, n] = W_sel[oc,:] . X[b,:,n] + bias
// oc in [0,32): wf/bf ; [32,64): wg/bg ; [64,192): wh/bh
// Tile 64x64, K-step 16, 256 threads, 4x4 per thread.
// ---------------------------------------------------------------------------
__global__ __launch_bounds__(256)
void proj_gemm(const float* __restrict__ x,
               const float* __restrict__ wf, const float* __restrict__ bf,
               const float* __restrict__ wg, const float* __restrict__ bg,
               const float* __restrict__ wh, const float* __restrict__ bh)
{
    __shared__ float As[16][68];   // [k][m]
    __shared__ float Bs[16][64];   // [k][n]

    const int b  = blockIdx.z;
    const int n0 = blockIdx.x * 64;
    const int m0 = blockIdx.y * 64;
    const float* xb = x + (size_t)b * C_IN * HW;

    const int tx = threadIdx.x & 15;
    const int ty = threadIdx.x >> 4;

    float acc[4][4];
    #pragma unroll
    for (int i = 0; i < 4; i++)
        #pragma unroll
        for (int j = 0; j < 4; j++) acc[i][j] = 0.f;

    for (int k0 = 0; k0 < C_IN; k0 += 16) {
        // A tile: 64 oc x 16 k
        for (int i = threadIdx.x; i < 64 * 16; i += 256) {
            int m = i >> 4, k = i & 15;
            int oc = m0 + m;
            const float* wr;
            if (oc < 32)       wr = wf + (size_t)oc * C_IN;
            else if (oc < 64)  wr = wg + (size_t)(oc - 32) * C_IN;
            else               wr = wh + (size_t)(oc - 64) * C_IN;
            As[k][m] = wr[k0 + k];
        }
        // B tile: 16 k x 64 n
        for (int i = threadIdx.x; i < 16 * 64; i += 256) {
            int k = i >> 6, n = i & 63;
            Bs[k][n] = xb[(size_t)(k0 + k) * HW + n0 + n];
        }
        __syncthreads();
        #pragma unroll
        for (int kk = 0; kk < 16; kk++) {
            float a[4], bb[4];
            #pragma unroll
            for (int i = 0; i < 4; i++) a[i] = As[kk][ty + 16 * i];
            #pragma unroll
            for (int j = 0; j < 4; j++) bb[j] = Bs[kk][tx + 16 * j];
            #pragma unroll
            for (int i = 0; i < 4; i++)
                #pragma unroll
                for (int j = 0; j < 4; j++) acc[i][j] += a[i] * bb[j];
        }
        __syncthreads();
    }

    #pragma unroll
    for (int i = 0; i < 4; i++) {
        int oc = m0 + ty + 16 * i;
        float bias;
        if (oc < 32)       bias = bf[oc];
        else if (oc < 64)  bias = bg[oc - 32];
        else               bias = bh[oc - 64];
        #pragma unroll
        for (int j = 0; j < 4; j++) {
            int n = n0 + tx + 16 * j;
            d_y[((size_t)b * OC_TOT + oc) * HW + n] = acc[i][j] + bias;
        }
    }
}

// ---------------------------------------------------------------------------
// Kernel 2: 2x2 maxpool for g/h channels (y channels 32..191)
// ---------------------------------------------------------------------------
__global__ __launch_bounds__(256)
void pool_kernel()
{
    int idx = blockIdx.x * 256 + threadIdx.x;
    const int total = BATCH * 160 * HWP;
    if (idx >= total) return;
    int l = idx & (HWP - 1);
    int t = idx >> 10;         // /HWP
    int c = t % 160;
    int b = t / 160;
    int ph = l >> 5, pw = l & 31;
    const float* src = d_y + ((size_t)b * OC_TOT + 32 + c) * HW;
    int base = (2 * ph) * W_DIM + 2 * pw;
    float v = fmaxf(fmaxf(src[base], src[base + 1]),
                    fmaxf(src[base + W_DIM], src[base + W_DIM + 1]));
    if (c < CK) d_gbuf[((size_t)b * CK + c) * HWP + l] = v;
    else        d_hbuf[((size_t)b * CH + (c - CK)) * HWP + l] = v;
}

// ---------------------------------------------------------------------------
// Kernel 3: fused attention (flash-style online softmax).
// Per CTA: batch b, 64 queries. Keys streamed in chunks of 128 (8 chunks).
// Thread t: query q = t&63, channel group cg = t>>6 (32 channels each).
// ---------------------------------------------------------------------------
#define TQ 64
#define LC 128
#define HPAD 132   // h stored transposed [l][c] padded
#define SPAD 129   // s rows padded

__global__ __launch_bounds__(256)
void attn_kernel()
{
    extern __shared__ float sm[];
    float* f_s = sm;                       // [32][64]
    float* g_s = f_s + 32 * 64;            // [32][128]
    float* h_s = g_s + 32 * LC;            // [128][HPAD]  (h transposed: [l][c])
    float* s_s = h_s + LC * HPAD;          // [64][SPAD]

    const int b  = blockIdx.y;
    const int q0 = blockIdx.x * TQ;
    const int t  = threadIdx.x;
    const int q  = t & 63;
    const int cg = t >> 6;
    const int cbase = cg * 32;
    const int lbase = cg * 32;

    const float* fb = d_y   + (size_t)b * OC_TOT * HW;   // channels 0..31 = f
    const float* gb = d_gbuf + (size_t)b * CK * HWP;
    const float* hb = d_hbuf + (size_t)b * CH * HWP;

    // load f tile [32 c][64 q]
    for (int i = t; i < 32 * 64; i += 256) {
        int c = i >> 6, qq = i & 63;
        f_s[c * 64 + qq] = fb[(size_t)c * HW + q0 + qq];
    }

    float acc[32];
    #pragma unroll
    for (int i = 0; i < 32; i++) acc[i] = 0.f;
    float m = -1e30f, dsum = 0.f;

    for (int lc = 0; lc < HWP; lc += LC) {
        __syncthreads();   // previous iteration's reads complete (covers f_s load on iter 0)
        // load g chunk [32][128]
        for (int i = t; i < 32 * LC; i += 256) {
            int c = i >> 7, l = i & 127;
            g_s[c * LC + l] = gb[(size_t)c * HWP + lc + l];
        }
        // load h chunk transposed: h_s[l][c]
        for (int i = t; i < CH * LC; i += 256) {
            int c = i >> 7, l = i & 127;
            h_s[l * HPAD + c] = hb[(size_t)c * HWP + lc + l];
        }
        __syncthreads();

        // --- S = f^T g for my (q, l-range) ---
        float sacc[32];
        #pragma unroll
        for (int i = 0; i < 32; i++) sacc[i] = 0.f;
        #pragma unroll 4
        for (int c = 0; c < 32; c++) {
            float fq = f_s[c * 64 + q];
            const float4* g4 = reinterpret_cast<const float4*>(&g_s[c * LC + lbase]);
            #pragma unroll
            for (int j = 0; j < 8; j++) {
                float4 gv = g4[j];
                sacc[4 * j + 0] += fq * gv.x;
                sacc[4 * j + 1] += fq * gv.y;
                sacc[4 * j + 2] += fq * gv.z;
                sacc[4 * j + 3] += fq * gv.w;
            }
        }
        #pragma unroll
        for (int i = 0; i < 32; i++) s_s[q * SPAD + lbase + i] = sacc[i];
        __syncthreads();

        // --- online softmax + O accumulation ---
        float mc = m;
        #pragma unroll 8
        for (int l = 0; l < LC; l++) mc = fmaxf(mc, s_s[q * SPAD + l]);
        float corr = __expf(m - mc);
        dsum *= corr;
        #pragma unroll
        for (int i = 0; i < 32; i++) acc[i] *= corr;

        #pragma unroll 2
        for (int l = 0; l < LC; l++) {
            float p = __expf(s_s[q * SPAD + l] - mc);
            dsum += p;
            const float4* h4 = reinterpret_cast<const float4*>(&h_s[l * HPAD + cbase]);
            #pragma unroll
            for (int j = 0; j < 8; j++) {
                float4 hv = h4[j];
                acc[4 * j + 0] += p * hv.x;
                acc[4 * j + 1] += p * hv.y;
                acc[4 * j + 2] += p * hv.z;
                acc[4 * j + 3] += p * hv.w;
            }
        }
        m = mc;
    }

    float inv = 1.f / dsum;
    #pragma unroll
    for (int i = 0; i < 32; i++)
        d_obuf[((size_t)b * CH + cbase + i) * HW + q0 + q] = acc[i] * inv;
}

// ---------------------------------------------------------------------------
// Kernel 4: out = gamma * (wv @ o + bv) + x
// M=256, N=4096, K=128 per batch. Same tiling as kernel 1.
// ---------------------------------------------------------------------------
__global__ __launch_bounds__(256)
void out_gemm(const float* __restrict__ x,
              const float* __restrict__ wv, const float* __restrict__ bv,
              const float* __restrict__ gamma_p, float* __restrict__ out)
{
    __shared__ float As[16][68];
    __shared__ float Bs[16][64];

    const int b  = blockIdx.z;
    const int n0 = blockIdx.x * 64;
    const int m0 = blockIdx.y * 64;
    const float* ob = d_obuf + (size_t)b * CH * HW;
    const float gamma = *gamma_p;

    const int tx = threadIdx.x & 15;
    const int ty = threadIdx.x >> 4;

    float acc[4][4];
    #pragma unroll
    for (int i = 0; i < 4; i++)
        #pragma unroll
        for (int j = 0; j < 4; j++) acc[i][j] = 0.f;

    for (int k0 = 0; k0 < CH; k0 += 16) {
        for (int i = threadIdx.x; i < 64 * 16; i += 256) {
            int mm = i >> 4, k = i & 15;
            As[k][mm] = wv[(size_t)(m0 + mm) * CH + k0 + k];
        }
        for (int i = threadIdx.x; i < 16 * 64; i += 256) {
            int k = i >> 6, n = i & 63;
            Bs[k][n] = ob[(size_t)(k0 + k) * HW + n0 + n];
        }
        __syncthreads();
        #pragma unroll
        for (int kk = 0; kk < 16; kk++) {
            float a[4], bb[4];
            #pragma unroll
            for (int i = 0; i < 4; i++) a[i] = As[kk][ty + 16 * i];
            #pragma unroll
            for (int j = 0; j < 4; j++) bb[j] = Bs[kk][tx + 16 * j];
            #pragma unroll
            for (int i = 0; i < 4; i++)
                #pragma unroll
                for (int j = 0; j < 4; j++) acc[i][j] += a[i] * bb[j];
        }
        __syncthreads();
    }

    #pragma unroll
    for (int i = 0; i < 4; i++) {
        int oc = m0 + ty + 16 * i;
        float bias = bv[oc];
        #pragma unroll
        for (int j = 0; j < 4; j++) {
            int n = n0 + tx + 16 * j;
            size_t idx = ((size_t)b * C_IN + oc) * HW + n;
            out[idx] = gamma * (acc[i][j] + bias) + x[idx];
        }
    }
}

// ---------------------------------------------------------------------------
extern "C" void kernel_launch(void* const* d_in, const int* in_sizes, int n_in,
                              void* d_out, int out_size)
{
    const float* x  = (const float*)d_in[0];
    const float* wf = (const float*)d_in[1];
    const float* bf = (const float*)d_in[2];
    const float* wg = (const float*)d_in[3];
    const float* bg = (const float*)d_in[4];
    const float* wh = (const float*)d_in[5];
    const float* bh = (const float*)d_in[6];
    const float* wv = (const float*)d_in[7];
    const float* bv = (const float*)d_in[8];
    const float* gamma = (const float*)d_in[9];
    float* out = (float*)d_out;

    // attention kernel needs >48KB dynamic smem
    const int attn_smem = (32 * 64 + 32 * LC + LC * HPAD + 64 * SPAD) * (int)sizeof(float);
    cudaFuncSetAttribute(attn_kernel, cudaFuncAttributeMaxDynamicSharedMemorySize, attn_smem);

    // 1) projections
    dim3 g1(HW / 64, OC_TOT / 64, BATCH);
    proj_gemm<<<g1, 256>>>(x, wf, bf, wg, bg, wh, bh);

    // 2) maxpool
    int pool_total = BATCH * 160 * HWP;
    pool_kernel<<<(pool_total + 255) / 256, 256>>>();

    // 3) attention
    dim3 g3(HW / TQ, BATCH);
    attn_kernel<<<g3, 256, attn_smem>>>();

    // 4) output conv + residual
    dim3 g4(HW / 64, C_IN / 64, BATCH);
    out_gemm<<<g4, 256>>>(x, wv, bv, gamma, out);
}

// round 2
// speedup vs baseline: 3.4414x; 3.4414x over previous
#include <cuda_runtime.h>
#include <cuda_bf16.h>
#include <stdint.h>
#include <math.h>

// Problem constants
#define BATCH 16
#define C_IN  256
#define W_DIM 64
#define HW    4096     // 64*64
#define HWP   1024     // pooled 32*32
#define CK    32       // f/g channels
#define CH    128      // h channels
#define OC_TOT 192     // 32(f)+32(g)+128(h)

// Scratch (static device globals -- allocation is forbidden)
__device__ float d_y[(size_t)BATCH * OC_TOT * HW];   // proj output full res
__device__ float d_gbuf[(size_t)BATCH * CK * HWP];   // pooled g
__device__ float d_hbuf[(size_t)BATCH * CH * HWP];   // pooled h
__device__ float d_obuf[(size_t)BATCH * HW * CH];    // attention out, layout [b][q][c]

// ---------------------------------------------------------------------------
// tf32 mma helpers (m16n8k8, A row-major, B col-major)
// ---------------------------------------------------------------------------
__device__ __forceinline__ uint32_t f2tf(float x) {
    uint32_t r;
    asm("cvt.rna.tf32.f32 %0, %1;" : "=r"(r) : "f"(x));
    return r;
}

__device__ __forceinline__ void mma8(float* d, const uint32_t* a, const uint32_t* b) {
    asm volatile(
        "mma.sync.aligned.m16n8k8.row.col.f32.tf32.tf32.f32 "
        "{%0,%1,%2,%3},{%4,%5,%6,%7},{%8,%9},{%0,%1,%2,%3};\n"
        : "+f"(d[0]), "+f"(d[1]), "+f"(d[2]), "+f"(d[3])
        : "r"(a[0]), "r"(a[1]), "r"(a[2]), "r"(a[3]), "r"(b[0]), "r"(b[1]));
}

// smem strides chosen so stride % 32 == 4 -> fragment LDS banks are (4*i + j), conflict-free
#define PAS 68    // A tile [k][m], m-dim 64
#define PBS 132   // B tile [k][n], n-dim 128
#define FS  36    // f tile [q][c], c-dim 32
#define GS  132   // g/h/p tiles, 128-dim

// ---------------------------------------------------------------------------
// Kernel 1: fused projection GEMM (tf32 mma). Y[b,oc,n] = W[oc,:].X[b,:,n]+bias
// Tile 64m x 128n, K chunks of 32. 8 warps as 2m x 4n, warp tile 32x32.
// ---------------------------------------------------------------------------
__global__ __launch_bounds__(256)
void proj_gemm(const float* __restrict__ x,
               const float* __restrict__ wf, const float* __restrict__ bf,
               const float* __restrict__ wg, const float* __restrict__ bg,
               const float* __restrict__ wh, const float* __restrict__ bh)
{
    __shared__ uint32_t As[32 * PAS];
    __shared__ uint32_t Bs[32 * PBS];

    const int b  = blockIdx.z;
    const int n0 = blockIdx.x * 128;
    const int m0 = blockIdx.y * 64;
    const float* xb = x + (size_t)b * C_IN * HW;

    const int t = threadIdx.x, lane = t & 31, wid = t >> 5;
    const int wm = wid & 1, wn = wid >> 1;

    float acc[2][4][4] = {};

    for (int k0 = 0; k0 < C_IN; k0 += 32) {
        // A tile: 64 oc x 32 k (float4 along k)
        #pragma unroll
        for (int ii = 0; ii < 2; ii++) {
            int i = t + ii * 256;                 // < 512
            int m = i >> 3, k4 = (i & 7) * 4;
            int oc = m0 + m;
            const float* wr;
            if (oc < 32)       wr = wf + (size_t)oc * C_IN;
            else if (oc < 64)  wr = wg + (size_t)(oc - 32) * C_IN;
            else               wr = wh + (size_t)(oc - 64) * C_IN;
            float4 v = *reinterpret_cast<const float4*>(wr + k0 + k4);
            As[(k4 + 0) * PAS + m] = f2tf(v.x);
            As[(k4 + 1) * PAS + m] = f2tf(v.y);
            As[(k4 + 2) * PAS + m] = f2tf(v.z);
            As[(k4 + 3) * PAS + m] = f2tf(v.w);
        }
        // B tile: 32 k x 128 n (float4 along n)
        #pragma unroll
        for (int ii = 0; ii < 4; ii++) {
            int i = t + ii * 256;                 // < 1024
            int k = i >> 5, n4 = (i & 31) * 4;
            float4 v = *reinterpret_cast<const float4*>(xb + (size_t)(k0 + k) * HW + n0 + n4);
            uint4 u = make_uint4(f2tf(v.x), f2tf(v.y), f2tf(v.z), f2tf(v.w));
            *reinterpret_cast<uint4*>(&Bs[k * PBS + n4]) = u;
        }
        __syncthreads();

        #pragma unroll
        for (int kk = 0; kk < 4; kk++) {
            int c = kk * 8 + (lane & 3);
            int r = lane >> 2;
            uint32_t a[2][4], bb[4][2];
            #pragma unroll
            for (int mt = 0; mt < 2; mt++) {
                int rb = wm * 32 + mt * 16 + r;
                a[mt][0] = As[c * PAS + rb];
                a[mt][1] = As[c * PAS + rb + 8];
                a[mt][2] = As[(c + 4) * PAS + rb];
                a[mt][3] = As[(c + 4) * PAS + rb + 8];
            }
            #pragma unroll
            for (int nt = 0; nt < 4; nt++) {
                int nb = wn * 32 + nt * 8 + r;
                bb[nt][0] = Bs[c * PBS + nb];
                bb[nt][1] = Bs[(c + 4) * PBS + nb];
            }
            #pragma unroll
            for (int mt = 0; mt < 2; mt++)
                #pragma unroll
                for (int nt = 0; nt < 4; nt++)
                    mma8(acc[mt][nt], a[mt], bb[nt]);
        }
        __syncthreads();
    }

    // epilogue: +bias, store
    #pragma unroll
    for (int mt = 0; mt < 2; mt++) {
        int r0 = m0 + wm * 32 + mt * 16 + (lane >> 2);
        #pragma unroll
        for (int dr = 0; dr < 2; dr++) {
            int oc = r0 + dr * 8;
            float bias = (oc < 32) ? bf[oc] : (oc < 64 ? bg[oc - 32] : bh[oc - 64]);
            float* dst = d_y + ((size_t)b * OC_TOT + oc) * HW + n0;
            #pragma unroll
            for (int nt = 0; nt < 4; nt++) {
                int cc = wn * 32 + nt * 8 + 2 * (lane & 3);
                float2 v = make_float2(acc[mt][nt][dr * 2 + 0] + bias,
                                       acc[mt][nt][dr * 2 + 1] + bias);
                *reinterpret_cast<float2*>(dst + cc) = v;
            }
        }
    }
}

// ---------------------------------------------------------------------------
// Kernel 2: 2x2 maxpool for g/h channels (y channels 32..191)
// ---------------------------------------------------------------------------
__global__ __launch_bounds__(256)
void pool_kernel()
{
    int idx = blockIdx.x * 256 + threadIdx.x;
    const int total = BATCH * 160 * HWP;
    if (idx >= total) return;
    int l = idx & (HWP - 1);
    int tt = idx >> 10;
    int c = tt % 160;
    int b = tt / 160;
    int ph = l >> 5, pw = l & 31;
    const float* src = d_y + ((size_t)b * OC_TOT + 32 + c) * HW;
    int base = (2 * ph) * W_DIM + 2 * pw;
    float v = fmaxf(fmaxf(src[base], src[base + 1]),
                    fmaxf(src[base + W_DIM], src[base + W_DIM + 1]));
    if (c < CK) d_gbuf[((size_t)b * CK + c) * HWP + l] = v;
    else        d_hbuf[((size_t)b * CH + (c - CK)) * HWP + l] = v;
}

// ---------------------------------------------------------------------------
// Kernel 3: fused flash attention with tf32 mma.
// Per CTA: 64 queries, l-chunks of 128. 8 warps as 2m x 4n.
// S[64,128] = f[64,32] g[32,128] -> smem -> softmax (online) -> P(tf32)
// O[64,128c] += P[64,128] * h^T  (B frag read straight from h[c][l])
// ---------------------------------------------------------------------------
__global__ __launch_bounds__(256)
void attn_kernel()
{
    extern __shared__ uint32_t sm[];
    uint32_t* f_s = sm;                  // [64][FS]  f as tf32
    uint32_t* g_s = f_s + 64 * FS;       // [32][GS]  g[c][l] tf32
    uint32_t* h_s = g_s + 32 * GS;       // [128][GS] h[c][l] tf32
    uint32_t* p_u = h_s + 128 * GS;      // [64][GS]  S scores (f32) then P (tf32)
    float* p_f   = reinterpret_cast<float*>(p_u);
    float* row_m = reinterpret_cast<float*>(p_u + 64 * GS);
    float* row_d = row_m + 64;
    float* row_c = row_d + 64;

    const int b  = blockIdx.y;
    const int q0 = blockIdx.x * 64;
    const int t = threadIdx.x, lane = t & 31, wid = t >> 5;
    const int wm = wid & 1, wn = wid >> 1;

    const float* fb = d_y    + (size_t)b * OC_TOT * HW;   // channels 0..31 = f
    const float* gb = d_gbuf + (size_t)b * CK * HWP;
    const float* hb = d_hbuf + (size_t)b * CH * HWP;

    // load f tile [64 q][32 c] (vectorized along q)
    #pragma unroll
    for (int ii = 0; ii < 2; ii++) {
        int i = t + ii * 256;               // < 512
        int c = i >> 4, q4 = (i & 15) * 4;
        float4 v = *reinterpret_cast<const float4*>(fb + (size_t)c * HW + q0 + q4);
        f_s[(q4 + 0) * FS + c] = f2tf(v.x);
        f_s[(q4 + 1) * FS + c] = f2tf(v.y);
        f_s[(q4 + 2) * FS + c] = f2tf(v.z);
        f_s[(q4 + 3) * FS + c] = f2tf(v.w);
    }
    if (t < 64) { row_m[t] = -1e30f; row_d[t] = 0.f; }

    float acc[2][4][4] = {};

    for (int lc = 0; lc < HWP; lc += 128) {
        __syncthreads();  // prev chunk's mma reads done; f/row init visible on iter 0

        // g chunk [32][128]
        #pragma unroll
        for (int ii = 0; ii < 4; ii++) {
            int i = t + ii * 256;              // < 1024
            int c = i >> 5, l4 = (i & 31) * 4;
            float4 v = *reinterpret_cast<const float4*>(gb + (size_t)c * HWP + lc + l4);
            uint4 u = make_uint4(f2tf(v.x), f2tf(v.y), f2tf(v.z), f2tf(v.w));
            *reinterpret_cast<uint4*>(&g_s[c * GS + l4]) = u;
        }
        // h chunk [128][128]
        #pragma unroll
        for (int ii = 0; ii < 16; ii++) {
            int i = t + ii * 256;              // < 4096
            int c = i >> 5, l4 = (i & 31) * 4;
            float4 v = *reinterpret_cast<const float4*>(hb + (size_t)c * HWP + lc + l4);
            uint4 u = make_uint4(f2tf(v.x), f2tf(v.y), f2tf(v.z), f2tf(v.w));
            *reinterpret_cast<uint4*>(&h_s[c * GS + l4]) = u;
        }
        __syncthreads();

        // --- S = f * g ---
        float sacc[2][4][4] = {};
        #pragma unroll
        for (int kk = 0; kk < 4; kk++) {
            int c = kk * 8 + (lane & 3);
            int r = lane >> 2;
            uint32_t a[2][4], bb[4][2];
            #pragma unroll
            for (int mt = 0; mt < 2; mt++) {
                int rb = wm * 32 + mt * 16 + r;
                a[mt][0] = f_s[rb * FS + c];
                a[mt][1] = f_s[(rb + 8) * FS + c];
                a[mt][2] = f_s[rb * FS + c + 4];
                a[mt][3] = f_s[(rb + 8) * FS + c + 4];
            }
            #pragma unroll
            for (int nt = 0; nt < 4; nt++) {
                int nb = wn * 32 + nt * 8 + r;
                bb[nt][0] = g_s[c * GS + nb];
                bb[nt][1] = g_s[(c + 4) * GS + nb];
            }
            #pragma unroll
            for (int mt = 0; mt < 2; mt++)
                #pragma unroll
                for (int nt = 0; nt < 4; nt++)
                    mma8(sacc[mt][nt], a[mt], bb[nt]);
        }
        // write raw S to p_f
        #pragma unroll
        for (int mt = 0; mt < 2; mt++) {
            int rb = wm * 32 + mt * 16 + (lane >> 2);
            #pragma unroll
            for (int nt = 0; nt < 4; nt++) {
                int cl = wn * 32 + nt * 8 + 2 * (lane & 3);
                *reinterpret_cast<float2*>(&p_f[rb * GS + cl]) =
                    make_float2(sacc[mt][nt][0], sacc[mt][nt][1]);
                *reinterpret_cast<float2*>(&p_f[(rb + 8) * GS + cl]) =
                    make_float2(sacc[mt][nt][2], sacc[mt][nt][3]);
            }
        }
        __syncthreads();

        // --- online softmax: 4 threads per row ---
        {
            int q = t >> 2, part = t & 3;
            float* rowp = p_f + q * GS + part * 32;
            uint32_t* rowu = p_u + q * GS + part * 32;
            float vmax = -1e30f;
            #pragma unroll
            for (int j = 0; j < 32; j++) vmax = fmaxf(vmax, rowp[j]);
            vmax = fmaxf(vmax, __shfl_xor_sync(0xffffffffu, vmax, 1));
            vmax = fmaxf(vmax, __shfl_xor_sync(0xffffffffu, vmax, 2));
            float mold = row_m[q];
            float mnew = fmaxf(mold, vmax);
            float lsum = 0.f;
            #pragma unroll
            for (int j = 0; j < 32; j++) {
                float p = __expf(rowp[j] - mnew);
                lsum += p;
                rowu[j] = f2tf(p);
            }
            lsum += __shfl_xor_sync(0xffffffffu, lsum, 1);
            lsum += __shfl_xor_sync(0xffffffffu, lsum, 2);
            if (part == 0) {
                float corr = __expf(mold - mnew);
                row_c[q] = corr;
                row_d[q] = row_d[q] * corr + lsum;
                row_m[q] = mnew;
            }
        }
        __syncthreads();

        // rescale running O accumulators
        #pragma unroll
        for (int mt = 0; mt < 2; mt++) {
            int rb = wm * 32 + mt * 16 + (lane >> 2);
            float ca = row_c[rb], cb2 = row_c[rb + 8];
            #pragma unroll
            for (int nt = 0; nt < 4; nt++) {
                acc[mt][nt][0] *= ca;  acc[mt][nt][1] *= ca;
                acc[mt][nt][2] *= cb2; acc[mt][nt][3] *= cb2;
            }
        }

        // --- O += P * h^T ---
        #pragma unroll
        for (int kk = 0; kk < 16; kk++) {
            int cl = kk * 8 + (lane & 3);    // l index
            int r = lane >> 2;
            uint32_t a[2][4], bb[4][2];
            #pragma unroll
            for (int mt = 0; mt < 2; mt++) {
                int rb = wm * 32 + mt * 16 + r;
                a[mt][0] = p_u[rb * GS + cl];
                a[mt][1] = p_u[(rb + 8) * GS + cl];
                a[mt][2] = p_u[rb * GS + cl + 4];
                a[mt][3] = p_u[(rb + 8) * GS + cl + 4];
            }
            #pragma unroll
            for (int nt = 0; nt < 4; nt++) {
                int nb = wn * 32 + nt * 8 + r;   // c channel
                bb[nt][0] = h_s[nb * GS + cl];
                bb[nt][1] = h_s[nb * GS + cl + 4];
            }
            #pragma unroll
            for (int mt = 0; mt < 2; mt++)
                #pragma unroll
                for (int nt = 0; nt < 4; nt++)
                    mma8(acc[mt][nt], a[mt], bb[nt]);
        }
    }

    // epilogue: normalize, store obuf [b][q][c]
    #pragma unroll
    for (int mt = 0; mt < 2; mt++) {
        int rb = wm * 32 + mt * 16 + (lane >> 2);
        float inv0 = 1.f / row_d[rb];
        float inv1 = 1.f / row_d[rb + 8];
        float* d0 = d_obuf + ((size_t)b * HW + q0 + rb) * CH;
        float* d1 = d_obuf + ((size_t)b * HW + q0 + rb + 8) * CH;
        #pragma unroll
        for (int nt = 0; nt < 4; nt++) {
            int cc = wn * 32 + nt * 8 + 2 * (lane & 3);
            *reinterpret_cast<float2*>(d0 + cc) =
                make_float2(acc[mt][nt][0] * inv0, acc[mt][nt][1] * inv0);
            *reinterpret_cast<float2*>(d1 + cc) =
                make_float2(acc[mt][nt][2] * inv1, acc[mt][nt][3] * inv1);
        }
    }
}

// ---------------------------------------------------------------------------
// Kernel 4: out = gamma * (wv @ o + bv) + x   (tf32 mma)
// M=256, N=4096, K=128. obuf layout [b][q][c] -> B[k=c][n=q].
// ---------------------------------------------------------------------------
__global__ __launch_bounds__(256)
void out_gemm(const float* __restrict__ x,
              const float* __restrict__ wv, const float* __restrict__ bv,
              const float* __restrict__ gamma_p, float* __restrict__ out)
{
    __shared__ uint32_t As[32 * PAS];
    __shared__ uint32_t Bs[32 * PBS];

    const int b  = blockIdx.z;
    const int n0 = blockIdx.x * 128;
    const int m0 = blockIdx.y * 64;
    const float* ob = d_obuf + (size_t)b * HW * CH;
    const float gamma = *gamma_p;

    const int t = threadIdx.x, lane = t & 31, wid = t >> 5;
    const int wm = wid & 1, wn = wid >> 1;

    float acc[2][4][4] = {};

    for (int k0 = 0; k0 < CH; k0 += 32) {
        // A tile: 64 oc x 32 c  (wv row-major [oc][CH])
        #pragma unroll
        for (int ii = 0; ii < 2; ii++) {
            int i = t + ii * 256;
            int m = i >> 3, k4 = (i & 7) * 4;
            float4 v = *reinterpret_cast<const float4*>(wv + (size_t)(m0 + m) * CH + k0 + k4);
            As[(k4 + 0) * PAS + m] = f2tf(v.x);
            As[(k4 + 1) * PAS + m] = f2tf(v.y);
            As[(k4 + 2) * PAS + m] = f2tf(v.z);
            As[(k4 + 3) * PAS + m] = f2tf(v.w);
        }
        // B tile: 32 c x 128 q  (obuf [q][c] -> transpose into Bs[c][q])
        #pragma unroll
        for (int ii = 0; ii < 4; ii++) {
            int i = t + ii * 256;              // < 1024
            int q = i >> 3, c4 = (i & 7) * 4;
            float4 v = *reinterpret_cast<const float4*>(ob + (size_t)(n0 + q) * CH + k0 + c4);
            Bs[(c4 + 0) * PBS + q] = f2tf(v.x);
            Bs[(c4 + 1) * PBS + q] = f2tf(v.y);
            Bs[(c4 + 2) * PBS + q] = f2tf(v.z);
            Bs[(c4 + 3) * PBS + q] = f2tf(v.w);
        }
        __syncthreads();

        #pragma unroll
        for (int kk = 0; kk < 4; kk++) {
            int c = kk * 8 + (lane & 3);
            int r = lane >> 2;
            uint32_t a[2][4], bb[4][2];
            #pragma unroll
            for (int mt = 0; mt < 2; mt++) {
                int rb = wm * 32 + mt * 16 + r;
                a[mt][0] = As[c * PAS + rb];
                a[mt][1] = As[c * PAS + rb + 8];
                a[mt][2] = As[(c + 4) * PAS + rb];
                a[mt][3] = As[(c + 4) * PAS + rb + 8];
            }
            #pragma unroll
            for (int nt = 0; nt < 4; nt++) {
                int nb = wn * 32 + nt * 8 + r;
                bb[nt][0] = Bs[c * PBS + nb];
                bb[nt][1] = Bs[(c + 4) * PBS + nb];
            }
            #pragma unroll
            for (int mt = 0; mt < 2; mt++)
                #pragma unroll
                for (int nt = 0; nt < 4; nt++)
                    mma8(acc[mt][nt], a[mt], bb[nt]);
        }
        __syncthreads();
    }

    // epilogue: gamma*(acc+bias) + x
    #pragma unroll
    for (int mt = 0; mt < 2; mt++) {
        int r0 = m0 + wm * 32 + mt * 16 + (lane >> 2);
        #pragma unroll
        for (int dr = 0; dr < 2; dr++) {
            int oc = r0 + dr * 8;
            float bias = bv[oc];
            size_t rowoff = ((size_t)b * C_IN + oc) * HW + n0;
            #pragma unroll
            for (int nt = 0; nt < 4; nt++) {
                int cc = wn * 32 + nt * 8 + 2 * (lane & 3);
                float2 xv = *reinterpret_cast<const float2*>(x + rowoff + cc);
                float2 v;
                v.x = gamma * (acc[mt][nt][dr * 2 + 0] + bias) + xv.x;
                v.y = gamma * (acc[mt][nt][dr * 2 + 1] + bias) + xv.y;
                *reinterpret_cast<float2*>(out + rowoff + cc) = v;
            }
        }
    }
}

// ---------------------------------------------------------------------------
extern "C" void kernel_launch(void* const* d_in, const int* in_sizes, int n_in,
                              void* d_out, int out_size)
{
    const float* x  = (const float*)d_in[0];
    const float* wf = (const float*)d_in[1];
    const float* bf = (const float*)d_in[2];
    const float* wg = (const float*)d_in[3];
    const float* bg = (const float*)d_in[4];
    const float* wh = (const float*)d_in[5];
    const float* bh = (const float*)d_in[6];
    const float* wv = (const float*)d_in[7];
    const float* bv = (const float*)d_in[8];
    const float* gamma = (const float*)d_in[9];
    float* out = (float*)d_out;

    const int attn_smem = (64 * FS + 32 * GS + 128 * GS + 64 * GS + 192) * (int)sizeof(uint32_t);
    cudaFuncSetAttribute(attn_kernel, cudaFuncAttributeMaxDynamicSharedMemorySize, attn_smem);

    // 1) projections (tf32 mma)
    dim3 g1(HW / 128, OC_TOT / 64, BATCH);
    proj_gemm<<<g1, 256>>>(x, wf, bf, wg, bg, wh, bh);

    // 2) maxpool
    int pool_total = BATCH * 160 * HWP;
    pool_kernel<<<(pool_total + 255) / 256, 256>>>();

    // 3) fused attention (tf32 mma)
    dim3 g3(HW / 64, BATCH);
    attn_kernel<<<g3, 256, attn_smem>>>();

    // 4) output conv + residual (tf32 mma)
    dim3 g4(HW / 128, C_IN / 64, BATCH);
    out_gemm<<<g4, 256>>>(x, wv, bv, gamma, out);
}

// round 3
// speedup vs baseline: 3.8596x; 1.1215x over previous
#include <cuda_runtime.h>
#include <cuda_bf16.h>
#include <stdint.h>
#include <math.h>

// Problem constants
#define BATCH 16
#define C_IN  256
#define W_DIM 64
#define HW    4096     // 64*64
#define HWP   1024     // pooled 32*32
#define CK    32       // f/g channels
#define CH    128      // h channels
#define OC_TOT 192

// Scratch (static device globals -- allocation is forbidden)
__device__ float d_f[(size_t)BATCH * CK * HW];       // f full res (8MB)
__device__ float d_gbuf[(size_t)BATCH * CK * HWP];   // pooled g
__device__ float d_hbuf[(size_t)BATCH * CH * HWP];   // pooled h
__device__ float d_obuf[(size_t)BATCH * HW * CH];    // attention out, layout [b][q][c]

// ---------------------------------------------------------------------------
// helpers
// ---------------------------------------------------------------------------
__device__ __forceinline__ uint32_t f2tf(float x) {
    uint32_t r;
    asm("cvt.rna.tf32.f32 %0, %1;" : "=r"(r) : "f"(x));
    return r;
}

__device__ __forceinline__ void mma8(float* d, const uint32_t* a, const uint32_t* b) {
    asm volatile(
        "mma.sync.aligned.m16n8k8.row.col.f32.tf32.tf32.f32 "
        "{%0,%1,%2,%3},{%4,%5,%6,%7},{%8,%9},{%0,%1,%2,%3};\n"
        : "+f"(d[0]), "+f"(d[1]), "+f"(d[2]), "+f"(d[3])
        : "r"(a[0]), "r"(a[1]), "r"(a[2]), "r"(a[3]), "r"(b[0]), "r"(b[1]));
}

__device__ __forceinline__ uint32_t s2u(const void* p) {
    return (uint32_t)__cvta_generic_to_shared(p);
}

// A fragment (m16 x k8 tf32) for mma row-major A. smem layout [m][k], rs words/row.
// thread t: row = m_base + (t&15), col = k_base + (t>>4)*4
__device__ __forceinline__ void ldsmA(uint32_t* r, const uint32_t* base, int rs,
                                      int m_base, int k_base, int lane) {
    const uint32_t* p = base + (size_t)(m_base + (lane & 15)) * rs + k_base + ((lane >> 4) << 2);
    uint32_t addr = s2u(p);
    asm volatile("ldmatrix.sync.aligned.m8n8.x4.shared.b16 {%0,%1,%2,%3},[%4];"
                 : "=r"(r[0]), "=r"(r[1]), "=r"(r[2]), "=r"(r[3]) : "r"(addr));
}

// B fragments for two n8 tiles (k8): smem layout [n][k], rs words/row.
// r0,r1 = {b0,b1} of n-tile at n_base ; r2,r3 = {b0,b1} of n-tile at n_base+8
__device__ __forceinline__ void ldsmB(uint32_t* r, const uint32_t* base, int rs,
                                      int n_base, int k_base, int lane) {
    int row = n_base + (lane & 7) + (((lane >> 4) & 1) << 3);
    int col = k_base + (((lane >> 3) & 1) << 2);
    const uint32_t* p = base + (size_t)row * rs + col;
    uint32_t addr = s2u(p);
    asm volatile("ldmatrix.sync.aligned.m8n8.x4.shared.b16 {%0,%1,%2,%3},[%4];"
                 : "=r"(r[0]), "=r"(r[1]), "=r"(r[2]), "=r"(r[3]) : "r"(addr));
}

#define RS36 36    // row pitch (words) for 32-wide k tiles: 144B = 16 mod 128 -> LDSM conflict-free
#define PS   132   // row pitch for 128-wide tiles (528B = 16 mod 128)

// ---------------------------------------------------------------------------
// Kernel 1: fused projection GEMM + bias + (for g/h) fused 2x2 maxpool.
// CTA tile 64m x 128n (=2 spatial rows), K=256 in chunks of 32.
// 8 warps as 2m x 4n, warp tile 32x32.
// oc<32 -> f (full res to d_f); 32..63 -> g pooled; 64..191 -> h pooled.
// ---------------------------------------------------------------------------
__global__ __launch_bounds__(256)
void proj_gemm(const float* __restrict__ x,
               const float* __restrict__ wf, const float* __restrict__ bf,
               const float* __restrict__ wg, const float* __restrict__ bg,
               const float* __restrict__ wh, const float* __restrict__ bh)
{
    __shared__ uint32_t As[64 * RS36];    // [m][k]
    __shared__ uint32_t Bs[128 * RS36];   // [n][k]

    const int b  = blockIdx.z;
    const int n0 = blockIdx.x * 128;
    const int m0 = blockIdx.y * 64;
    const float* xb = x + (size_t)b * C_IN * HW;

    const int t = threadIdx.x, lane = t & 31, wid = t >> 5;
    const int wm = wid & 1, wn = wid >> 1;

    float acc[2][4][4] = {};

    for (int k0 = 0; k0 < C_IN; k0 += 32) {
        // A tile: [64 m][32 k], float4 along k
        #pragma unroll
        for (int ii = 0; ii < 2; ii++) {
            int i = t + ii * 256;
            int m = i >> 3, k4 = (i & 7) * 4;
            int oc = m0 + m;
            const float* wr;
            if (oc < 32)       wr = wf + (size_t)oc * C_IN;
            else if (oc < 64)  wr = wg + (size_t)(oc - 32) * C_IN;
            else               wr = wh + (size_t)(oc - 64) * C_IN;
            float4 v = *reinterpret_cast<const float4*>(wr + k0 + k4);
            uint4 u = make_uint4(f2tf(v.x), f2tf(v.y), f2tf(v.z), f2tf(v.w));
            *reinterpret_cast<uint4*>(&As[m * RS36 + k4]) = u;
        }
        // B tile transposed: Bs[n][k]; 4 LDG along k (coalesced over n)
        #pragma unroll
        for (int ii = 0; ii < 4; ii++) {
            int i = t + ii * 256;                  // < 1024
            int n  = (i & 31) + ((i >> 5) & 3) * 32;
            int k4 = (i >> 7) * 4;
            uint4 u;
            u.x = f2tf(xb[(size_t)(k0 + k4 + 0) * HW + n0 + n]);
            u.y = f2tf(xb[(size_t)(k0 + k4 + 1) * HW + n0 + n]);
            u.z = f2tf(xb[(size_t)(k0 + k4 + 2) * HW + n0 + n]);
            u.w = f2tf(xb[(size_t)(k0 + k4 + 3) * HW + n0 + n]);
            *reinterpret_cast<uint4*>(&Bs[n * RS36 + k4]) = u;
        }
        __syncthreads();

        #pragma unroll
        for (int kk = 0; kk < 4; kk++) {
            uint32_t a0[4], a1[4], b01[4], b23[4];
            ldsmA(a0, As, RS36, wm * 32,      kk * 8, lane);
            ldsmA(a1, As, RS36, wm * 32 + 16, kk * 8, lane);
            ldsmB(b01, Bs, RS36, wn * 32,      kk * 8, lane);
            ldsmB(b23, Bs, RS36, wn * 32 + 16, kk * 8, lane);
            mma8(acc[0][0], a0, b01); mma8(acc[0][1], a0, b01 + 2);
            mma8(acc[0][2], a0, b23); mma8(acc[0][3], a0, b23 + 2);
            mma8(acc[1][0], a1, b01); mma8(acc[1][1], a1, b01 + 2);
            mma8(acc[1][2], a1, b23); mma8(acc[1][3], a1, b23 + 2);
        }
        __syncthreads();
    }

    // ---- epilogue: f full-res store; g/h fused 2x2 maxpool ----
    float* psm = reinterpret_cast<float*>(Bs);   // [64 ocl][2 rows][32 pw] = 4096 floats

    #pragma unroll
    for (int mt = 0; mt < 2; mt++) {
        #pragma unroll
        for (int dr = 0; dr < 2; dr++) {
            int ocl = wm * 32 + mt * 16 + dr * 8 + (lane >> 2);
            int oc = m0 + ocl;
            #pragma unroll
            for (int nt = 0; nt < 4; nt++) {
                int nloc = wn * 32 + nt * 8 + 2 * (lane & 3);
                float v0 = acc[mt][nt][dr * 2 + 0];
                float v1 = acc[mt][nt][dr * 2 + 1];
                if (oc < 32) {
                    float bias = bf[oc];
                    *reinterpret_cast<float2*>(
                        d_f + ((size_t)b * CK + oc) * HW + n0 + nloc) =
                        make_float2(v0 + bias, v1 + bias);
                } else {
                    int pr = nloc >> 6;
                    int pw = (nloc & 63) >> 1;
                    psm[ocl * 64 + pr * 32 + pw] = fmaxf(v0, v1);
                }
            }
        }
    }
    __syncthreads();

    int ph = n0 >> 7;   // pooled spatial row
    for (int i = t; i < 64 * 32; i += 256) {
        int ocl = i >> 5, pw = i & 31;
        int oc = m0 + ocl;
        if (oc >= 32) {
            float v = fmaxf(psm[ocl * 64 + pw], psm[ocl * 64 + 32 + pw]);
            if (oc < 64)
                d_gbuf[((size_t)b * CK + oc - 32) * HWP + ph * 32 + pw] = v + bg[oc - 32];
            else
                d_hbuf[((size_t)b * CH + oc - 64) * HWP + ph * 32 + pw] = v + bh[oc - 64];
        }
    }
}

// ---------------------------------------------------------------------------
// Kernel 2: fused flash attention with tf32 mma + ldmatrix.
// Per CTA: 64 queries, l-chunks of 128. 8 warps as 2m x 4n.
// ---------------------------------------------------------------------------
__global__ __launch_bounds__(256)
void attn_kernel()
{
    extern __shared__ uint32_t sm[];
    uint32_t* f_s = sm;                   // [64 q][RS36]   A for S (k=c)
    uint32_t* g_s = f_s + 64 * RS36;      // [128 l][RS36]  B for S (n=l,k=c)
    uint32_t* h_s = g_s + 128 * RS36;     // [128 c][PS]    B for O (n=c,k=l)
    uint32_t* p_u = h_s + 128 * PS;       // [64 q][PS]     S (f32) then P (tf32); A for O
    float* p_f   = reinterpret_cast<float*>(p_u);
    float* row_m = reinterpret_cast<float*>(p_u + 64 * PS);
    float* row_d = row_m + 64;
    float* row_c = row_d + 64;

    const int b  = blockIdx.y;
    const int q0 = blockIdx.x * 64;
    const int t = threadIdx.x, lane = t & 31, wid = t >> 5;
    const int wm = wid & 1, wn = wid >> 1;

    const float* fb = d_f    + (size_t)b * CK * HW;
    const float* gb = d_gbuf + (size_t)b * CK * HWP;
    const float* hb = d_hbuf + (size_t)b * CH * HWP;

    // f tile: f_s[q][c] via 4 LDG along c (coalesced over q)
    #pragma unroll
    for (int ii = 0; ii < 2; ii++) {
        int i = t + ii * 256;                 // < 512
        int q = i & 63, c4 = (i >> 6) * 4;
        uint4 u;
        u.x = f2tf(fb[(size_t)(c4 + 0) * HW + q0 + q]);
        u.y = f2tf(fb[(size_t)(c4 + 1) * HW + q0 + q]);
        u.z = f2tf(fb[(size_t)(c4 + 2) * HW + q0 + q]);
        u.w = f2tf(fb[(size_t)(c4 + 3) * HW + q0 + q]);
        *reinterpret_cast<uint4*>(&f_s[q * RS36 + c4]) = u;
    }
    if (t < 64) { row_m[t] = -1e30f; row_d[t] = 0.f; }

    float acc[2][4][4] = {};

    for (int lc = 0; lc < HWP; lc += 128) {
        __syncthreads();   // prev chunk reads done; f/rows visible on iter 0

        // g chunk: g_s[l][c] via 4 LDG along c (coalesced over l)
        #pragma unroll
        for (int ii = 0; ii < 4; ii++) {
            int i = t + ii * 256;             // < 1024
            int l  = (i & 31) + ((i >> 5) & 3) * 32;
            int c4 = (i >> 7) * 4;
            uint4 u;
            u.x = f2tf(gb[(size_t)(c4 + 0) * HWP + lc + l]);
            u.y = f2tf(gb[(size_t)(c4 + 1) * HWP + lc + l]);
            u.z = f2tf(gb[(size_t)(c4 + 2) * HWP + lc + l]);
            u.w = f2tf(gb[(size_t)(c4 + 3) * HWP + lc + l]);
            *reinterpret_cast<uint4*>(&g_s[l * RS36 + c4]) = u;
        }
        // h chunk: h_s[c][l] native (LDG.128 along l)
        #pragma unroll
        for (int ii = 0; ii < 16; ii++) {
            int i = t + ii * 256;             // < 4096
            int c = i >> 5, l4 = (i & 31) * 4;
            float4 v = *reinterpret_cast<const float4*>(hb + (size_t)c * HWP + lc + l4);
            uint4 u = make_uint4(f2tf(v.x), f2tf(v.y), f2tf(v.z), f2tf(v.w));
            *reinterpret_cast<uint4*>(&h_s[c * PS + l4]) = u;
        }
        __syncthreads();

        // --- S = f * g ---
        float sacc[2][4][4] = {};
        #pragma unroll
        for (int kk = 0; kk < 4; kk++) {
            uint32_t a0[4], a1[4], b01[4], b23[4];
            ldsmA(a0, f_s, RS36, wm * 32,      kk * 8, lane);
            ldsmA(a1, f_s, RS36, wm * 32 + 16, kk * 8, lane);
            ldsmB(b01, g_s, RS36, wn * 32,      kk * 8, lane);
            ldsmB(b23, g_s, RS36, wn * 32 + 16, kk * 8, lane);
            mma8(sacc[0][0], a0, b01); mma8(sacc[0][1], a0, b01 + 2);
            mma8(sacc[0][2], a0, b23); mma8(sacc[0][3], a0, b23 + 2);
            mma8(sacc[1][0], a1, b01); mma8(sacc[1][1], a1, b01 + 2);
            mma8(sacc[1][2], a1, b23); mma8(sacc[1][3], a1, b23 + 2);
        }
        // write raw S
        #pragma unroll
        for (int mt = 0; mt < 2; mt++) {
            int rb = wm * 32 + mt * 16 + (lane >> 2);
            #pragma unroll
            for (int nt = 0; nt < 4; nt++) {
                int cl = wn * 32 + nt * 8 + 2 * (lane & 3);
                *reinterpret_cast<float2*>(&p_f[rb * PS + cl]) =
                    make_float2(sacc[mt][nt][0], sacc[mt][nt][1]);
                *reinterpret_cast<float2*>(&p_f[(rb + 8) * PS + cl]) =
                    make_float2(sacc[mt][nt][2], sacc[mt][nt][3]);
            }
        }
        __syncthreads();

        // --- online softmax: 4 threads per row, vectorized ---
        {
            int q = t >> 2, part = t & 3;
            float*    rowp = p_f + q * PS + part * 32;
            uint32_t* rowu = p_u + q * PS + part * 32;
            float vmax = -1e30f;
            #pragma unroll
            for (int j = 0; j < 8; j++) {
                float4 v = reinterpret_cast<const float4*>(rowp)[j];
                vmax = fmaxf(vmax, fmaxf(fmaxf(v.x, v.y), fmaxf(v.z, v.w)));
            }
            vmax = fmaxf(vmax, __shfl_xor_sync(0xffffffffu, vmax, 1));
            vmax = fmaxf(vmax, __shfl_xor_sync(0xffffffffu, vmax, 2));
            float mold = row_m[q];
            float mnew = fmaxf(mold, vmax);
            float lsum = 0.f;
            #pragma unroll
            for (int j = 0; j < 8; j++) {
                float4 v = reinterpret_cast<const float4*>(rowp)[j];
                float p0 = __expf(v.x - mnew), p1 = __expf(v.y - mnew);
                float p2 = __expf(v.z - mnew), p3 = __expf(v.w - mnew);
                lsum += (p0 + p1) + (p2 + p3);
                reinterpret_cast<uint4*>(rowu)[j] =
                    make_uint4(f2tf(p0), f2tf(p1), f2tf(p2), f2tf(p3));
            }
            lsum += __shfl_xor_sync(0xffffffffu, lsum, 1);
            lsum += __shfl_xor_sync(0xffffffffu, lsum, 2);
            if (part == 0) {
                float corr = __expf(mold - mnew);
                row_c[q] = corr;
                row_d[q] = row_d[q] * corr + lsum;
                row_m[q] = mnew;
            }
        }
        __syncthreads();

        // rescale running O accumulators
        #pragma unroll
        for (int mt = 0; mt < 2; mt++) {
            int rb = wm * 32 + mt * 16 + (lane >> 2);
            float ca = row_c[rb], cb2 = row_c[rb + 8];
            #pragma unroll
            for (int nt = 0; nt < 4; nt++) {
                acc[mt][nt][0] *= ca;  acc[mt][nt][1] *= ca;
                acc[mt][nt][2] *= cb2; acc[mt][nt][3] *= cb2;
            }
        }

        // --- O += P * h^T ---
        #pragma unroll
        for (int kk = 0; kk < 16; kk++) {
            uint32_t a0[4], a1[4], b01[4], b23[4];
            ldsmA(a0, p_u, PS, wm * 32,      kk * 8, lane);
            ldsmA(a1, p_u, PS, wm * 32 + 16, kk * 8, lane);
            ldsmB(b01, h_s, PS, wn * 32,      kk * 8, lane);
            ldsmB(b23, h_s, PS, wn * 32 + 16, kk * 8, lane);
            mma8(acc[0][0], a0, b01); mma8(acc[0][1], a0, b01 + 2);
            mma8(acc[0][2], a0, b23); mma8(acc[0][3], a0, b23 + 2);
            mma8(acc[1][0], a1, b01); mma8(acc[1][1], a1, b01 + 2);
            mma8(acc[1][2], a1, b23); mma8(acc[1][3], a1, b23 + 2);
        }
    }

    // epilogue: normalize, store obuf [b][q][c]
    #pragma unroll
    for (int mt = 0; mt < 2; mt++) {
        int rb = wm * 32 + mt * 16 + (lane >> 2);
        float inv0 = 1.f / row_d[rb];
        float inv1 = 1.f / row_d[rb + 8];
        float* d0 = d_obuf + ((size_t)b * HW + q0 + rb) * CH;
        float* d1 = d_obuf + ((size_t)b * HW + q0 + rb + 8) * CH;
        #pragma unroll
        for (int nt = 0; nt < 4; nt++) {
            int cc = wn * 32 + nt * 8 + 2 * (lane & 3);
            *reinterpret_cast<float2*>(d0 + cc) =
                make_float2(acc[mt][nt][0] * inv0, acc[mt][nt][1] * inv0);
            *reinterpret_cast<float2*>(d1 + cc) =
                make_float2(acc[mt][nt][2] * inv1, acc[mt][nt][3] * inv1);
        }
    }
}

// ---------------------------------------------------------------------------
// Kernel 3: out = gamma * (wv @ o + bv) + x   (tf32 mma + ldmatrix)
// M=256, N=4096, K=128. obuf layout [b][q][c] is already [n][k].
// ---------------------------------------------------------------------------
__global__ __launch_bounds__(256)
void out_gemm(const float* __restrict__ x,
              const float* __restrict__ wv, const float* __restrict__ bv,
              const float* __restrict__ gamma_p, float* __restrict__ out)
{
    __shared__ uint32_t As[64 * RS36];
    __shared__ uint32_t Bs[128 * RS36];

    const int b  = blockIdx.z;
    const int n0 = blockIdx.x * 128;
    const int m0 = blockIdx.y * 64;
    const float* ob = d_obuf + (size_t)b * HW * CH;
    const float gamma = *gamma_p;

    const int t = threadIdx.x, lane = t & 31, wid = t >> 5;
    const int wm = wid & 1, wn = wid >> 1;

    float acc[2][4][4] = {};

    for (int k0 = 0; k0 < CH; k0 += 32) {
        // A tile [64 m][32 k]
        #pragma unroll
        for (int ii = 0; ii < 2; ii++) {
            int i = t + ii * 256;
            int m = i >> 3, k4 = (i & 7) * 4;
            float4 v = *reinterpret_cast<const float4*>(wv + (size_t)(m0 + m) * CH + k0 + k4);
            uint4 u = make_uint4(f2tf(v.x), f2tf(v.y), f2tf(v.z), f2tf(v.w));
            *reinterpret_cast<uint4*>(&As[m * RS36 + k4]) = u;
        }
        // B tile [128 n=q][32 k=c], native obuf layout (LDG.128 along c)
        #pragma unroll
        for (int ii = 0; ii < 4; ii++) {
            int i = t + ii * 256;              // < 1024
            int q = i >> 3, c4 = (i & 7) * 4;
            float4 v = *reinterpret_cast<const float4*>(ob + (size_t)(n0 + q) * CH + k0 + c4);
            uint4 u = make_uint4(f2tf(v.x), f2tf(v.y), f2tf(v.z), f2tf(v.w));
            *reinterpret_cast<uint4*>(&Bs[q * RS36 + c4]) = u;
        }
        __syncthreads();

        #pragma unroll
        for (int kk = 0; kk < 4; kk++) {
            uint32_t a0[4], a1[4], b01[4], b23[4];
            ldsmA(a0, As, RS36, wm * 32,      kk * 8, lane);
            ldsmA(a1, As, RS36, wm * 32 + 16, kk * 8, lane);
            ldsmB(b01, Bs, RS36, wn * 32,      kk * 8, lane);
            ldsmB(b23, Bs, RS36, wn * 32 + 16, kk * 8, lane);
            mma8(acc[0][0], a0, b01); mma8(acc[0][1], a0, b01 + 2);
            mma8(acc[0][2], a0, b23); mma8(acc[0][3], a0, b23 + 2);
            mma8(acc[1][0], a1, b01); mma8(acc[1][1], a1, b01 + 2);
            mma8(acc[1][2], a1, b23); mma8(acc[1][3], a1, b23 + 2);
        }
        __syncthreads();
    }

    // epilogue: gamma*(acc+bias) + x
    #pragma unroll
    for (int mt = 0; mt < 2; mt++) {
        int r0 = m0 + wm * 32 + mt * 16 + (lane >> 2);
        #pragma unroll
        for (int dr = 0; dr < 2; dr++) {
            int oc = r0 + dr * 8;
            float bias = bv[oc];
            size_t rowoff = ((size_t)b * C_IN + oc) * HW + n0;
            #pragma unroll
            for (int nt = 0; nt < 4; nt++) {
                int cc = wn * 32 + nt * 8 + 2 * (lane & 3);
                float2 xv = *reinterpret_cast<const float2*>(x + rowoff + cc);
                float2 v;
                v.x = gamma * (acc[mt][nt][dr * 2 + 0] + bias) + xv.x;
                v.y = gamma * (acc[mt][nt][dr * 2 + 1] + bias) + xv.y;
                *reinterpret_cast<float2*>(out + rowoff + cc) = v;
            }
        }
    }
}

// ---------------------------------------------------------------------------
extern "C" void kernel_launch(void* const* d_in, const int* in_sizes, int n_in,
                              void* d_out, int out_size)
{
    const float* x  = (const float*)d_in[0];
    const float* wf = (const float*)d_in[1];
    const float* bf = (const float*)d_in[2];
    const float* wg = (const float*)d_in[3];
    const float* bg = (const float*)d_in[4];
    const float* wh = (const float*)d_in[5];
    const float* bh = (const float*)d_in[6];
    const float* wv = (const float*)d_in[7];
    const float* bv = (const float*)d_in[8];
    const float* gamma = (const float*)d_in[9];
    float* out = (float*)d_out;

    const int attn_smem = (64 * RS36 + 128 * RS36 + 128 * PS + 64 * PS + 192) * (int)sizeof(uint32_t);
    cudaFuncSetAttribute(attn_kernel, cudaFuncAttributeMaxDynamicSharedMemorySize, attn_smem);

    // 1) projections + fused pool
    dim3 g1(HW / 128, OC_TOT / 64, BATCH);
    proj_gemm<<<g1, 256>>>(x, wf, bf, wg, bg, wh, bh);

    // 2) fused attention
    dim3 g3(HW / 64, BATCH);
    attn_kernel<<<g3, 256, attn_smem>>>();

    // 3) output conv + residual
    dim3 g4(HW / 128, C_IN / 64, BATCH);
    out_gemm<<<g4, 256>>>(x, wv, bv, gamma, out);
}

// round 4
// speedup vs baseline: 5.0079x; 1.2975x over previous
#include <cuda_runtime.h>
#include <cuda_bf16.h>
#include <stdint.h>
#include <math.h>

// Problem constants
#define BATCH 16
#define C_IN  256
#define W_DIM 64
#define HW    4096     // 64*64
#define HWP   1024     // pooled 32*32
#define CK    32       // f/g channels
#define CH    128      // h channels
#define OC_TOT 192

// Scratch (static device globals). f/g/h/obuf hold tf32 bit patterns.
__device__ uint32_t d_f[(size_t)BATCH * CK * HW];
__device__ uint32_t d_gbuf[(size_t)BATCH * CK * HWP];
__device__ uint32_t d_hbuf[(size_t)BATCH * CH * HWP];
__device__ uint32_t d_obuf[(size_t)BATCH * HW * CH];   // [b][q][c]

// ---------------------------------------------------------------------------
// helpers
// ---------------------------------------------------------------------------
__device__ __forceinline__ uint32_t f2tf(float x) {
    uint32_t r;
    asm("cvt.rna.tf32.f32 %0, %1;" : "=r"(r) : "f"(x));
    return r;
}

__device__ __forceinline__ void mma8(float* d, const uint32_t* a, const uint32_t* b) {
    asm volatile(
        "mma.sync.aligned.m16n8k8.row.col.f32.tf32.tf32.f32 "
        "{%0,%1,%2,%3},{%4,%5,%6,%7},{%8,%9},{%0,%1,%2,%3};\n"
        : "+f"(d[0]), "+f"(d[1]), "+f"(d[2]), "+f"(d[3])
        : "r"(a[0]), "r"(a[1]), "r"(a[2]), "r"(a[3]), "r"(b[0]), "r"(b[1]));
}

__device__ __forceinline__ uint32_t s2u(const void* p) {
    return (uint32_t)__cvta_generic_to_shared(p);
}

__device__ __forceinline__ void cp16(void* dst, const void* src) {
    asm volatile("cp.async.cg.shared.global [%0], [%1], 16;\n"
                 :: "r"(s2u(dst)), "l"(src));
}
__device__ __forceinline__ void cp4(void* dst, const void* src) {
    asm volatile("cp.async.ca.shared.global [%0], [%1], 4;\n"
                 :: "r"(s2u(dst)), "l"(src));
}
__device__ __forceinline__ void cp_commit() {
    asm volatile("cp.async.commit_group;\n" ::);
}
__device__ __forceinline__ void cp_wait_all() {
    asm volatile("cp.async.wait_group 0;\n" ::);
}

// A fragment (m16 x k8 tf32), smem layout [m][k], rs words/row
__device__ __forceinline__ void ldsmA(uint32_t* r, const uint32_t* base, int rs,
                                      int m_base, int k_base, int lane) {
    const uint32_t* p = base + (size_t)(m_base + (lane & 15)) * rs + k_base + ((lane >> 4) << 2);
    uint32_t addr = s2u(p);
    asm volatile("ldmatrix.sync.aligned.m8n8.x4.shared.b16 {%0,%1,%2,%3},[%4];"
                 : "=r"(r[0]), "=r"(r[1]), "=r"(r[2]), "=r"(r[3]) : "r"(addr));
}

// B fragments for two n8 tiles (k8), smem layout [n][k]
__device__ __forceinline__ void ldsmB(uint32_t* r, const uint32_t* base, int rs,
                                      int n_base, int k_base, int lane) {
    int row = n_base + (lane & 7) + (((lane >> 4) & 1) << 3);
    int col = k_base + (((lane >> 3) & 1) << 2);
    const uint32_t* p = base + (size_t)row * rs + col;
    uint32_t addr = s2u(p);
    asm volatile("ldmatrix.sync.aligned.m8n8.x4.shared.b16 {%0,%1,%2,%3},[%4];"
                 : "=r"(r[0]), "=r"(r[1]), "=r"(r[2]), "=r"(r[3]) : "r"(addr));
}

#define RS36 36    // pitch (words), 144B = 16 mod 128 -> LDSM conflict-free
#define PS   132   // pitch for 128-wide k tiles

// ---------------------------------------------------------------------------
// Kernel 1: fused projection GEMM + bias + (g/h) fused 2x2 maxpool.
// Outputs tf32 bit patterns.
// ---------------------------------------------------------------------------
__global__ __launch_bounds__(256)
void proj_gemm(const float* __restrict__ x,
               const float* __restrict__ wf, const float* __restrict__ bf,
               const float* __restrict__ wg, const float* __restrict__ bg,
               const float* __restrict__ wh, const float* __restrict__ bh)
{
    __shared__ uint32_t As[64 * RS36];    // [m][k]
    __shared__ uint32_t Bs[128 * RS36];   // [n][k]

    const int b  = blockIdx.z;
    const int n0 = blockIdx.x * 128;
    const int m0 = blockIdx.y * 64;
    const float* xb = x + (size_t)b * C_IN * HW;

    const int t = threadIdx.x, lane = t & 31, wid = t >> 5;
    const int wm = wid & 1, wn = wid >> 1;

    float acc[2][4][4] = {};

    for (int k0 = 0; k0 < C_IN; k0 += 32) {
        #pragma unroll
        for (int ii = 0; ii < 2; ii++) {
            int i = t + ii * 256;
            int m = i >> 3, k4 = (i & 7) * 4;
            int oc = m0 + m;
            const float* wr;
            if (oc < 32)       wr = wf + (size_t)oc * C_IN;
            else if (oc < 64)  wr = wg + (size_t)(oc - 32) * C_IN;
            else               wr = wh + (size_t)(oc - 64) * C_IN;
            float4 v = *reinterpret_cast<const float4*>(wr + k0 + k4);
            uint4 u = make_uint4(f2tf(v.x), f2tf(v.y), f2tf(v.z), f2tf(v.w));
            *reinterpret_cast<uint4*>(&As[m * RS36 + k4]) = u;
        }
        #pragma unroll
        for (int ii = 0; ii < 4; ii++) {
            int i = t + ii * 256;
            int n  = (i & 31) + ((i >> 5) & 3) * 32;
            int k4 = (i >> 7) * 4;
            uint4 u;
            u.x = f2tf(xb[(size_t)(k0 + k4 + 0) * HW + n0 + n]);
            u.y = f2tf(xb[(size_t)(k0 + k4 + 1) * HW + n0 + n]);
            u.z = f2tf(xb[(size_t)(k0 + k4 + 2) * HW + n0 + n]);
            u.w = f2tf(xb[(size_t)(k0 + k4 + 3) * HW + n0 + n]);
            *reinterpret_cast<uint4*>(&Bs[n * RS36 + k4]) = u;
        }
        __syncthreads();

        #pragma unroll
        for (int kk = 0; kk < 4; kk++) {
            uint32_t a0[4], a1[4], b01[4], b23[4];
            ldsmA(a0, As, RS36, wm * 32,      kk * 8, lane);
            ldsmA(a1, As, RS36, wm * 32 + 16, kk * 8, lane);
            ldsmB(b01, Bs, RS36, wn * 32,      kk * 8, lane);
            ldsmB(b23, Bs, RS36, wn * 32 + 16, kk * 8, lane);
            mma8(acc[0][0], a0, b01); mma8(acc[0][1], a0, b01 + 2);
            mma8(acc[0][2], a0, b23); mma8(acc[0][3], a0, b23 + 2);
            mma8(acc[1][0], a1, b01); mma8(acc[1][1], a1, b01 + 2);
            mma8(acc[1][2], a1, b23); mma8(acc[1][3], a1, b23 + 2);
        }
        __syncthreads();
    }

    // epilogue
    float* psm = reinterpret_cast<float*>(Bs);   // [64][2][32]

    #pragma unroll
    for (int mt = 0; mt < 2; mt++) {
        #pragma unroll
        for (int dr = 0; dr < 2; dr++) {
            int ocl = wm * 32 + mt * 16 + dr * 8 + (lane >> 2);
            int oc = m0 + ocl;
            #pragma unroll
            for (int nt = 0; nt < 4; nt++) {
                int nloc = wn * 32 + nt * 8 + 2 * (lane & 3);
                float v0 = acc[mt][nt][dr * 2 + 0];
                float v1 = acc[mt][nt][dr * 2 + 1];
                if (oc < 32) {
                    float bias = bf[oc];
                    *reinterpret_cast<uint2*>(
                        d_f + ((size_t)b * CK + oc) * HW + n0 + nloc) =
                        make_uint2(f2tf(v0 + bias), f2tf(v1 + bias));
                } else {
                    int pr = nloc >> 6;
                    int pw = (nloc & 63) >> 1;
                    psm[ocl * 64 + pr * 32 + pw] = fmaxf(v0, v1);
                }
            }
        }
    }
    __syncthreads();

    int ph = n0 >> 7;
    for (int i = t; i < 64 * 32; i += 256) {
        int ocl = i >> 5, pw = i & 31;
        int oc = m0 + ocl;
        if (oc >= 32) {
            float v = fmaxf(psm[ocl * 64 + pw], psm[ocl * 64 + 32 + pw]);
            if (oc < 64)
                d_gbuf[((size_t)b * CK + oc - 32) * HWP + ph * 32 + pw] = f2tf(v + bg[oc - 32]);
            else
                d_hbuf[((size_t)b * CH + oc - 64) * HWP + ph * 32 + pw] = f2tf(v + bh[oc - 64]);
        }
    }
}

// ---------------------------------------------------------------------------
// Kernel 2: fused flash attention, no-max softmax, cp.async double buffering.
// Per CTA: 64 queries, 8 l-chunks of 128. 8 warps as 2m x 4n.
// ---------------------------------------------------------------------------
__global__ __launch_bounds__(256)
void attn_kernel()
{
    extern __shared__ uint32_t sm[];
    uint32_t* f_s = sm;                         // [64][RS36]
    uint32_t* g_s = f_s + 64 * RS36;            // 2 x [128 l][RS36]
    uint32_t* h_s = g_s + 2 * 128 * RS36;       // 2 x [128 c][PS]
    uint32_t* p_u = h_s + 2 * 128 * PS;         // [64 q][PS]  P (tf32)
    float* row_part = reinterpret_cast<float*>(p_u + 64 * PS);  // [4 wn][64]

    const int b  = blockIdx.y;
    const int q0 = blockIdx.x * 64;
    const int t = threadIdx.x, lane = t & 31, wid = t >> 5;
    const int wm = wid & 1, wn = wid >> 1;

    const uint32_t* fb = d_f    + (size_t)b * CK * HW;
    const uint32_t* gb = d_gbuf + (size_t)b * CK * HWP;
    const uint32_t* hb = d_hbuf + (size_t)b * CH * HWP;

    // issue async loads of one l-chunk into buffer `buf`
    auto issue_chunk = [&](int lc, int buf) {
        uint32_t* gd = g_s + buf * 128 * RS36;
        uint32_t* hd = h_s + buf * 128 * PS;
        #pragma unroll
        for (int ii = 0; ii < 4; ii++) {
            int i = t + ii * 256;
            int l  = (i & 31) + ((i >> 5) & 3) * 32;
            int c4 = (i >> 7) * 4;
            #pragma unroll
            for (int j = 0; j < 4; j++)
                cp4(&gd[l * RS36 + c4 + j], gb + (size_t)(c4 + j) * HWP + lc + l);
        }
        #pragma unroll
        for (int ii = 0; ii < 16; ii++) {
            int i = t + ii * 256;
            int c = i >> 5, l4 = (i & 31) * 4;
            cp16(&hd[c * PS + l4], hb + (size_t)c * HWP + lc + l4);
        }
        cp_commit();
    };

    issue_chunk(0, 0);

    // f tile [64 q][32 c] (raw tf32 bits)
    #pragma unroll
    for (int ii = 0; ii < 2; ii++) {
        int i = t + ii * 256;
        int q = i & 63, c4 = (i >> 6) * 4;
        uint4 u;
        u.x = fb[(size_t)(c4 + 0) * HW + q0 + q];
        u.y = fb[(size_t)(c4 + 1) * HW + q0 + q];
        u.z = fb[(size_t)(c4 + 2) * HW + q0 + q];
        u.w = fb[(size_t)(c4 + 3) * HW + q0 + q];
        *reinterpret_cast<uint4*>(&f_s[q * RS36 + c4]) = u;
    }

    float acc[2][4][4] = {};
    float rsum[2][2] = {};   // [mt][half] partial row sums, accumulated over all chunks

    for (int ic = 0; ic < 8; ic++) {
        cp_wait_all();
        __syncthreads();                 // chunk ic data visible; prev compute done
        if (ic + 1 < 8) issue_chunk((ic + 1) * 128, (ic + 1) & 1);

        const uint32_t* gbuf = g_s + (ic & 1) * 128 * RS36;
        const uint32_t* hbuf = h_s + (ic & 1) * 128 * PS;

        // --- S = f * g ---
        float sacc[2][4][4] = {};
        #pragma unroll
        for (int kk = 0; kk < 4; kk++) {
            uint32_t a0[4], a1[4], b01[4], b23[4];
            ldsmA(a0, f_s, RS36, wm * 32,      kk * 8, lane);
            ldsmA(a1, f_s, RS36, wm * 32 + 16, kk * 8, lane);
            ldsmB(b01, gbuf, RS36, wn * 32,      kk * 8, lane);
            ldsmB(b23, gbuf, RS36, wn * 32 + 16, kk * 8, lane);
            mma8(sacc[0][0], a0, b01); mma8(sacc[0][1], a0, b01 + 2);
            mma8(sacc[0][2], a0, b23); mma8(sacc[0][3], a0, b23 + 2);
            mma8(sacc[1][0], a1, b01); mma8(sacc[1][1], a1, b01 + 2);
            mma8(sacc[1][2], a1, b23); mma8(sacc[1][3], a1, b23 + 2);
        }

        // --- exp on fragments, partial sums, store P (tf32) ---
        #pragma unroll
        for (int mt = 0; mt < 2; mt++) {
            int rb = wm * 32 + mt * 16 + (lane >> 2);
            #pragma unroll
            for (int nt = 0; nt < 4; nt++) {
                int cl = wn * 32 + nt * 8 + 2 * (lane & 3);
                float p0 = __expf(sacc[mt][nt][0]);
                float p1 = __expf(sacc[mt][nt][1]);
                float p2 = __expf(sacc[mt][nt][2]);
                float p3 = __expf(sacc[mt][nt][3]);
                rsum[mt][0] += p0 + p1;
                rsum[mt][1] += p2 + p3;
                *reinterpret_cast<uint2*>(&p_u[rb * PS + cl]) =
                    make_uint2(f2tf(p0), f2tf(p1));
                *reinterpret_cast<uint2*>(&p_u[(rb + 8) * PS + cl]) =
                    make_uint2(f2tf(p2), f2tf(p3));
            }
        }
        __syncthreads();

        // --- O += P * h^T ---
        #pragma unroll
        for (int kk = 0; kk < 16; kk++) {
            uint32_t a0[4], a1[4], b01[4], b23[4];
            ldsmA(a0, p_u, PS, wm * 32,      kk * 8, lane);
            ldsmA(a1, p_u, PS, wm * 32 + 16, kk * 8, lane);
            ldsmB(b01, hbuf, PS, wn * 32,      kk * 8, lane);
            ldsmB(b23, hbuf, PS, wn * 32 + 16, kk * 8, lane);
            mma8(acc[0][0], a0, b01); mma8(acc[0][1], a0, b01 + 2);
            mma8(acc[0][2], a0, b23); mma8(acc[0][3], a0, b23 + 2);
            mma8(acc[1][0], a1, b01); mma8(acc[1][1], a1, b01 + 2);
            mma8(acc[1][2], a1, b23); mma8(acc[1][3], a1, b23 + 2);
        }
    }

    // --- final row-sum reduction: over lane&3 (shfl), then across 4 wn warps ---
    #pragma unroll
    for (int mt = 0; mt < 2; mt++)
        #pragma unroll
        for (int hh = 0; hh < 2; hh++) {
            float s = rsum[mt][hh];
            s += __shfl_xor_sync(0xffffffffu, s, 1);
            s += __shfl_xor_sync(0xffffffffu, s, 2);
            rsum[mt][hh] = s;
        }
    if ((lane & 3) == 0) {
        #pragma unroll
        for (int mt = 0; mt < 2; mt++)
            #pragma unroll
            for (int hh = 0; hh < 2; hh++) {
                int rb = wm * 32 + mt * 16 + hh * 8 + (lane >> 2);
                row_part[wn * 64 + rb] = rsum[mt][hh];
            }
    }
    __syncthreads();

    // epilogue: normalize, store obuf [b][q][c] as tf32 bits
    #pragma unroll
    for (int mt = 0; mt < 2; mt++) {
        int rb = wm * 32 + mt * 16 + (lane >> 2);
        float d0 = row_part[rb]      + row_part[64 + rb]      + row_part[128 + rb]      + row_part[192 + rb];
        float d1 = row_part[rb + 8]  + row_part[64 + rb + 8]  + row_part[128 + rb + 8]  + row_part[192 + rb + 8];
        float inv0 = 1.f / d0;
        float inv1 = 1.f / d1;
        uint32_t* o0 = d_obuf + ((size_t)b * HW + q0 + rb) * CH;
        uint32_t* o1 = d_obuf + ((size_t)b * HW + q0 + rb + 8) * CH;
        #pragma unroll
        for (int nt = 0; nt < 4; nt++) {
            int cc = wn * 32 + nt * 8 + 2 * (lane & 3);
            *reinterpret_cast<uint2*>(o0 + cc) =
                make_uint2(f2tf(acc[mt][nt][0] * inv0), f2tf(acc[mt][nt][1] * inv0));
            *reinterpret_cast<uint2*>(o1 + cc) =
                make_uint2(f2tf(acc[mt][nt][2] * inv1), f2tf(acc[mt][nt][3] * inv1));
        }
    }
}

// ---------------------------------------------------------------------------
// Kernel 3: out = gamma * (wv @ o + bv) + x   (obuf already tf32 bits)
// ---------------------------------------------------------------------------
__global__ __launch_bounds__(256)
void out_gemm(const float* __restrict__ x,
              const float* __restrict__ wv, const float* __restrict__ bv,
              const float* __restrict__ gamma_p, float* __restrict__ out)
{
    __shared__ uint32_t As[64 * RS36];
    __shared__ uint32_t Bs[128 * RS36];

    const int b  = blockIdx.z;
    const int n0 = blockIdx.x * 128;
    const int m0 = blockIdx.y * 64;
    const uint32_t* ob = d_obuf + (size_t)b * HW * CH;
    const float gamma = *gamma_p;

    const int t = threadIdx.x, lane = t & 31, wid = t >> 5;
    const int wm = wid & 1, wn = wid >> 1;

    float acc[2][4][4] = {};

    for (int k0 = 0; k0 < CH; k0 += 32) {
        #pragma unroll
        for (int ii = 0; ii < 2; ii++) {
            int i = t + ii * 256;
            int m = i >> 3, k4 = (i & 7) * 4;
            float4 v = *reinterpret_cast<const float4*>(wv + (size_t)(m0 + m) * CH + k0 + k4);
            uint4 u = make_uint4(f2tf(v.x), f2tf(v.y), f2tf(v.z), f2tf(v.w));
            *reinterpret_cast<uint4*>(&As[m * RS36 + k4]) = u;
        }
        #pragma unroll
        for (int ii = 0; ii < 4; ii++) {
            int i = t + ii * 256;
            int q = i >> 3, c4 = (i & 7) * 4;
            uint4 u = *reinterpret_cast<const uint4*>(ob + (size_t)(n0 + q) * CH + k0 + c4);
            *reinterpret_cast<uint4*>(&Bs[q * RS36 + c4]) = u;
        }
        __syncthreads();

        #pragma unroll
        for (int kk = 0; kk < 4; kk++) {
            uint32_t a0[4], a1[4], b01[4], b23[4];
            ldsmA(a0, As, RS36, wm * 32,      kk * 8, lane);
            ldsmA(a1, As, RS36, wm * 32 + 16, kk * 8, lane);
            ldsmB(b01, Bs, RS36, wn * 32,      kk * 8, lane);
            ldsmB(b23, Bs, RS36, wn * 32 + 16, kk * 8, lane);
            mma8(acc[0][0], a0, b01); mma8(acc[0][1], a0, b01 + 2);
            mma8(acc[0][2], a0, b23); mma8(acc[0][3], a0, b23 + 2);
            mma8(acc[1][0], a1, b01); mma8(acc[1][1], a1, b01 + 2);
            mma8(acc[1][2], a1, b23); mma8(acc[1][3], a1, b23 + 2);
        }
        __syncthreads();
    }

    #pragma unroll
    for (int mt = 0; mt < 2; mt++) {
        int r0 = m0 + wm * 32 + mt * 16 + (lane >> 2);
        #pragma unroll
        for (int dr = 0; dr < 2; dr++) {
            int oc = r0 + dr * 8;
            float bias = bv[oc];
            size_t rowoff = ((size_t)b * C_IN + oc) * HW + n0;
            #pragma unroll
            for (int nt = 0; nt < 4; nt++) {
                int cc = wn * 32 + nt * 8 + 2 * (lane & 3);
                float2 xv = *reinterpret_cast<const float2*>(x + rowoff + cc);
                float2 v;
                v.x = gamma * (acc[mt][nt][dr * 2 + 0] + bias) + xv.x;
                v.y = gamma * (acc[mt][nt][dr * 2 + 1] + bias) + xv.y;
                *reinterpret_cast<float2*>(out + rowoff + cc) = v;
            }
        }
    }
}

// ---------------------------------------------------------------------------
extern "C" void kernel_launch(void* const* d_in, const int* in_sizes, int n_in,
                              void* d_out, int out_size)
{
    const float* x  = (const float*)d_in[0];
    const float* wf = (const float*)d_in[1];
    const float* bf = (const float*)d_in[2];
    const float* wg = (const float*)d_in[3];
    const float* bg = (const float*)d_in[4];
    const float* wh = (const float*)d_in[5];
    const float* bh = (const float*)d_in[6];
    const float* wv = (const float*)d_in[7];
    const float* bv = (const float*)d_in[8];
    const float* gamma = (const float*)d_in[9];
    float* out = (float*)d_out;

    const int attn_smem =
        (64 * RS36 + 2 * 128 * RS36 + 2 * 128 * PS + 64 * PS + 256) * (int)sizeof(uint32_t);
    cudaFuncSetAttribute(attn_kernel, cudaFuncAttributeMaxDynamicSharedMemorySize, attn_smem);

    dim3 g1(HW / 128, OC_TOT / 64, BATCH);
    proj_gemm<<<g1, 256>>>(x, wf, bf, wg, bg, wh, bh);

    dim3 g3(HW / 64, BATCH);
    attn_kernel<<<g3, 256, attn_smem>>>();

    dim3 g4(HW / 128, C_IN / 64, BATCH);
    out_gemm<<<g4, 256>>>(x, wv, bv, gamma, out);
}